// round 2
// baseline (speedup 1.0000x reference)
#include <cuda_runtime.h>
#include <math_constants.h>

#define N_NODES 50000
#define N_EDGES 640000
#define D 128

// Scratch (static device globals are the sanctioned scratch mechanism)
__device__ float g_h[N_NODES * D];       // pooled features, 25.6 MB
__device__ float g_neigh[N_NODES * D];   // scatter-max accumulator, 25.6 MB
__device__ int   g_is64;                 // index dtype flag

// ---------------------------------------------------------------------------
// Detect whether src/dst are int64 or int32: for int64 little-endian values
// < 2^32, every odd 32-bit word is zero. For int32 random indices in
// [0,50000), the chance all 32 sampled words are zero is ~(1/50000)^32.
// ---------------------------------------------------------------------------
__global__ void detect_kernel(const int* __restrict__ s32) {
    int ok = 1;
    for (int i = 1; i < 64; i += 2) {
        if (s32[i] != 0) { ok = 0; break; }
    }
    g_is64 = ok;
}

__global__ void init_kernel() {
    int stride = gridDim.x * blockDim.x;
    for (int i = blockIdx.x * blockDim.x + threadIdx.x; i < N_NODES * D; i += stride)
        g_neigh[i] = -CUDART_INF_F;
}

// ---------------------------------------------------------------------------
// GEMM1: g_h = feat @ W_pool^T + b_pool     (A: [N,128], W: [128,128])
// Block: 256 threads. sW staged once (padded stride K+1 -> conflict-free),
// 8-row A tiles (padded stride K+4 -> 16B-aligned float4 broadcast reads).
// ---------------------------------------------------------------------------
__global__ void gemm_pool_kernel(const float* __restrict__ feat,
                                 const float* __restrict__ W,
                                 const float* __restrict__ bias) {
    const int K = 128;
    extern __shared__ float sh[];
    float* sW = sh;                      // 128 x 129
    float* sA = sh + 128 * (K + 1);      // 8 x 132
    const int tid = threadIdx.x;

    for (int t = tid; t < 128 * K; t += blockDim.x) {
        int r = t >> 7, c = t & 127;
        sW[r * (K + 1) + c] = W[t];
    }

    const int j  = tid & 127;       // output column
    const int rg = tid >> 7;        // row group: rows rg*4 .. rg*4+3
    const float b = bias[j];
    const int numTiles = N_NODES / 8;   // 6250 (exact)

    for (int tile = blockIdx.x; tile < numTiles; tile += gridDim.x) {
        const int row0 = tile * 8;
        __syncthreads();
        for (int t = tid; t < 8 * K; t += blockDim.x) {
            int r = t >> 7, c = t & 127;
            sA[r * (K + 4) + c] = feat[(row0 + r) * K + c];
        }
        __syncthreads();

        float acc0 = b, acc1 = b, acc2 = b, acc3 = b;
        const float* wrow = &sW[j * (K + 1)];
        const float* arow = &sA[(rg * 4) * (K + 4)];
        #pragma unroll 8
        for (int k = 0; k < K; k += 4) {
            float w0 = wrow[k], w1 = wrow[k + 1], w2 = wrow[k + 2], w3 = wrow[k + 3];
            float4 a0 = *(const float4*)&arow[0 * (K + 4) + k];
            float4 a1 = *(const float4*)&arow[1 * (K + 4) + k];
            float4 a2 = *(const float4*)&arow[2 * (K + 4) + k];
            float4 a3 = *(const float4*)&arow[3 * (K + 4) + k];
            acc0 += a0.x * w0 + a0.y * w1 + a0.z * w2 + a0.w * w3;
            acc1 += a1.x * w0 + a1.y * w1 + a1.z * w2 + a1.w * w3;
            acc2 += a2.x * w0 + a2.y * w1 + a2.z * w2 + a2.w * w3;
            acc3 += a3.x * w0 + a3.y * w1 + a3.z * w2 + a3.w * w3;
        }
        const int rb = row0 + rg * 4;
        g_h[(rb + 0) * D + j] = acc0;
        g_h[(rb + 1) * D + j] = acc1;
        g_h[(rb + 2) * D + j] = acc2;
        g_h[(rb + 3) * D + j] = acc3;
    }
}

// ---------------------------------------------------------------------------
// Edge scatter-max: one warp per edge, 4 floats per lane.
// Signed-float atomic max via int max / uint min trick (no return -> RED).
// ---------------------------------------------------------------------------
__device__ __forceinline__ void atomicMaxF(float* addr, float val) {
    if (val >= 0.0f) atomicMax((int*)addr, __float_as_int(val));
    else             atomicMin((unsigned int*)addr, __float_as_uint(val));
}

__global__ void edge_kernel(const void* __restrict__ srcp,
                            const void* __restrict__ dstp,
                            const float* __restrict__ w) {
    const int warp = blockIdx.x * (blockDim.x >> 5) + (threadIdx.x >> 5);
    const int lane = threadIdx.x & 31;
    if (warp >= N_EDGES) return;

    long long s, d;
    if (g_is64) {
        s = ((const long long*)srcp)[warp];
        d = ((const long long*)dstp)[warp];
    } else {
        s = ((const int*)srcp)[warp];
        d = ((const int*)dstp)[warp];
    }
    const float we = w[warp];
    const float4 h4 = *(const float4*)&g_h[(int)s * D + lane * 4];
    float* np = &g_neigh[(int)d * D + lane * 4];
    atomicMaxF(np + 0, h4.x * we);
    atomicMaxF(np + 1, h4.y * we);
    atomicMaxF(np + 2, h4.z * we);
    atomicMaxF(np + 3, h4.w * we);
}

// ---------------------------------------------------------------------------
// GEMM2: out = concat(feat, neigh') @ W_neigh^T + b_neigh   (K = 256)
// neigh' clamps -inf (zero-degree) to 0 at staging time.
// ---------------------------------------------------------------------------
__global__ void gemm_out_kernel(const float* __restrict__ feat,
                                const float* __restrict__ W,
                                const float* __restrict__ bias,
                                float* __restrict__ out) {
    const int K = 256;
    extern __shared__ float sh[];
    float* sW = sh;                      // 128 x 257
    float* sA = sh + 128 * (K + 1);      // 8 x 260
    const int tid = threadIdx.x;

    for (int t = tid; t < 128 * K; t += blockDim.x) {
        int r = t >> 8, c = t & 255;
        sW[r * (K + 1) + c] = W[t];
    }

    const int j  = tid & 127;
    const int rg = tid >> 7;
    const float b = bias[j];
    const int numTiles = N_NODES / 8;

    for (int tile = blockIdx.x; tile < numTiles; tile += gridDim.x) {
        const int row0 = tile * 8;
        __syncthreads();
        for (int t = tid; t < 8 * K; t += blockDim.x) {
            int r = t >> 8, c = t & 255;
            int row = row0 + r;
            float v;
            if (c < 128) {
                v = feat[row * D + c];
            } else {
                v = g_neigh[row * D + (c - 128)];
                if (v == -CUDART_INF_F) v = 0.0f;   // zero-degree fixup
            }
            sA[r * (K + 4) + c] = v;
        }
        __syncthreads();

        float acc0 = b, acc1 = b, acc2 = b, acc3 = b;
        const float* wrow = &sW[j * (K + 1)];
        const float* arow = &sA[(rg * 4) * (K + 4)];
        #pragma unroll 8
        for (int k = 0; k < K; k += 4) {
            float w0 = wrow[k], w1 = wrow[k + 1], w2 = wrow[k + 2], w3 = wrow[k + 3];
            float4 a0 = *(const float4*)&arow[0 * (K + 4) + k];
            float4 a1 = *(const float4*)&arow[1 * (K + 4) + k];
            float4 a2 = *(const float4*)&arow[2 * (K + 4) + k];
            float4 a3 = *(const float4*)&arow[3 * (K + 4) + k];
            acc0 += a0.x * w0 + a0.y * w1 + a0.z * w2 + a0.w * w3;
            acc1 += a1.x * w0 + a1.y * w1 + a1.z * w2 + a1.w * w3;
            acc2 += a2.x * w0 + a2.y * w1 + a2.z * w2 + a2.w * w3;
            acc3 += a3.x * w0 + a3.y * w1 + a3.z * w2 + a3.w * w3;
        }
        const int rb = row0 + rg * 4;
        out[(rb + 0) * D + j] = acc0;
        out[(rb + 1) * D + j] = acc1;
        out[(rb + 2) * D + j] = acc2;
        out[(rb + 3) * D + j] = acc3;
    }
}

// ---------------------------------------------------------------------------
extern "C" void kernel_launch(void* const* d_in, const int* in_sizes, int n_in,
                              void* d_out, int out_size) {
    const float* feat    = (const float*)d_in[0];
    const float* weight  = (const float*)d_in[1];
    const void*  src     = d_in[2];
    const void*  dst     = d_in[3];
    const float* W_pool  = (const float*)d_in[4];
    const float* b_pool  = (const float*)d_in[5];
    const float* W_neigh = (const float*)d_in[6];
    const float* b_neigh = (const float*)d_in[7];
    float* out = (float*)d_out;

    const int shm1 = (128 * 129 + 8 * 132) * sizeof(float);   // 70272 B
    const int shm2 = (128 * 257 + 8 * 260) * sizeof(float);   // 139904 B
    cudaFuncSetAttribute(gemm_pool_kernel, cudaFuncAttributeMaxDynamicSharedMemorySize, shm1);
    cudaFuncSetAttribute(gemm_out_kernel,  cudaFuncAttributeMaxDynamicSharedMemorySize, shm2);

    detect_kernel<<<1, 1>>>((const int*)src);
    init_kernel<<<592, 256>>>();
    gemm_pool_kernel<<<444, 256, shm1>>>(feat, W_pool, b_pool);
    edge_kernel<<<N_EDGES / 8, 256>>>(src, dst, weight);
    gemm_out_kernel<<<148, 256, shm2>>>(feat, W_neigh, b_neigh, out);
}

// round 7
// speedup vs baseline: 3.2575x; 3.2575x over previous
#include <cuda_runtime.h>
#include <math_constants.h>

#define N_NODES 50000
#define N_EDGES 640000
#define D 128

// ---------------- scratch ----------------
__device__ float g_h[N_NODES * D];        // pooled features
__device__ float g_neigh[N_NODES * D];    // max-aggregated messages (0 for deg-0)
__device__ int   g_deg[N_NODES];
__device__ int   g_off[N_NODES + 1];
__device__ int   g_cur[N_NODES];
__device__ int   g_bsum[128];
__device__ int   g_boff[128];
__device__ int   g_srcs[N_EDGES];         // dst-sorted src ids
__device__ float g_ws[N_EDGES];           // dst-sorted weights
__device__ int   g_is64;

// ---------------------------------------------------------------------------
// int64 vs int32 index detection (odd 32-bit words of LE int64 < 2^32 are 0)
// ---------------------------------------------------------------------------
__global__ void detect_kernel(const int* __restrict__ s32) {
    int ok = 1;
    for (int i = 1; i < 64; i += 2)
        if (s32[i] != 0) { ok = 0; break; }
    g_is64 = ok;
}

__global__ void zero_deg_kernel() {
    int i = blockIdx.x * blockDim.x + threadIdx.x;
    if (i < N_NODES) g_deg[i] = 0;
}

__global__ void hist_kernel(const void* __restrict__ dstp) {
    int e = blockIdx.x * blockDim.x + threadIdx.x;
    if (e >= N_EDGES) return;
    int d = g_is64 ? (int)((const long long*)dstp)[e] : ((const int*)dstp)[e];
    atomicAdd(&g_deg[d], 1);
}

// ----- 3-phase exclusive scan over 50000 degrees (block = 512) -----
__global__ void scan1_kernel() {
    __shared__ int tmp[512];
    int t = threadIdx.x, i = blockIdx.x * 512 + t;
    int v = (i < N_NODES) ? g_deg[i] : 0;
    tmp[t] = v;
    __syncthreads();
    for (int off = 1; off < 512; off <<= 1) {
        int x = tmp[t];
        if (t >= off) x += tmp[t - off];
        __syncthreads();
        tmp[t] = x;
        __syncthreads();
    }
    int incl = tmp[t];
    if (i < N_NODES) g_off[i] = incl - v;      // local exclusive
    if (t == 511) g_bsum[blockIdx.x] = incl;   // block total
}

__global__ void scan2_kernel(int nb) {
    int run = 0;
    for (int b = 0; b < nb; b++) { g_boff[b] = run; run += g_bsum[b]; }
    g_off[N_NODES] = run;   // == N_EDGES
}

__global__ void scan3_kernel() {
    int i = blockIdx.x * 512 + threadIdx.x;
    if (i < N_NODES) {
        int o = g_off[i] + g_boff[blockIdx.x];
        g_off[i] = o;
        g_cur[i] = o;
    }
}

__global__ void scatter_kernel(const void* __restrict__ srcp,
                               const void* __restrict__ dstp,
                               const float* __restrict__ w) {
    int e = blockIdx.x * blockDim.x + threadIdx.x;
    if (e >= N_EDGES) return;
    int s, d;
    if (g_is64) {
        s = (int)((const long long*)srcp)[e];
        d = (int)((const long long*)dstp)[e];
    } else {
        s = ((const int*)srcp)[e];
        d = ((const int*)dstp)[e];
    }
    int pos = atomicAdd(&g_cur[d], 1);
    g_srcs[pos] = s;
    g_ws[pos]   = w[e];
}

// ---------------------------------------------------------------------------
// Gather-max: one warp per node. Atomic-free; max is order-invariant.
// ---------------------------------------------------------------------------
__global__ void gather_kernel() {
    const int node = blockIdx.x * 8 + (threadIdx.x >> 5);
    const int lane = threadIdx.x & 31;
    if (node >= N_NODES) return;
    const int beg = g_off[node], end = g_off[node + 1];

    float4 acc = make_float4(-CUDART_INF_F, -CUDART_INF_F, -CUDART_INF_F, -CUDART_INF_F);
    int e = beg;
    for (; e + 1 < end; e += 2) {
        int   s0 = g_srcs[e],   s1 = g_srcs[e + 1];
        float w0 = g_ws[e],     w1 = g_ws[e + 1];
        float4 h0 = *(const float4*)&g_h[s0 * D + lane * 4];
        float4 h1 = *(const float4*)&g_h[s1 * D + lane * 4];
        acc.x = fmaxf(acc.x, h0.x * w0); acc.y = fmaxf(acc.y, h0.y * w0);
        acc.z = fmaxf(acc.z, h0.z * w0); acc.w = fmaxf(acc.w, h0.w * w0);
        acc.x = fmaxf(acc.x, h1.x * w1); acc.y = fmaxf(acc.y, h1.y * w1);
        acc.z = fmaxf(acc.z, h1.z * w1); acc.w = fmaxf(acc.w, h1.w * w1);
    }
    if (e < end) {
        int s0 = g_srcs[e]; float w0 = g_ws[e];
        float4 h0 = *(const float4*)&g_h[s0 * D + lane * 4];
        acc.x = fmaxf(acc.x, h0.x * w0); acc.y = fmaxf(acc.y, h0.y * w0);
        acc.z = fmaxf(acc.z, h0.z * w0); acc.w = fmaxf(acc.w, h0.w * w0);
    }
    if (beg == end) acc = make_float4(0.f, 0.f, 0.f, 0.f);
    *(float4*)&g_neigh[node * D + lane * 4] = acc;
}

// ---------------------------------------------------------------------------
// GEMM1: g_h = feat @ W_pool^T + b  (K=128). 512 thr, tile 128 rows x 128 cols.
// Each thread: 8 rows x 4 cols, k-vectorized float4 loads (A broadcast, W coalesced).
// ---------------------------------------------------------------------------
__global__ void __launch_bounds__(512, 1)
gemm_pool_kernel(const float* __restrict__ feat,
                 const float* __restrict__ W,
                 const float* __restrict__ bias) {
    const int K = 128;
    extern __shared__ float sh[];
    float* sWT = sh;                 // [K][128] k-major
    float* sA  = sh + K * 128;       // [128][K+4]
    const int tid = threadIdx.x;

    // stage W transposed: sWT[k*128 + j] = W[j*K + k]
    {
        int j = tid & 127;
        for (int kb = (tid >> 7) * 4; kb < K; kb += 16) {
            float4 v = *(const float4*)&W[j * K + kb];
            sWT[(kb + 0) * 128 + j] = v.x;
            sWT[(kb + 1) * 128 + j] = v.y;
            sWT[(kb + 2) * 128 + j] = v.z;
            sWT[(kb + 3) * 128 + j] = v.w;
        }
    }

    const int rg = tid >> 5;            // 0..15
    const int jg = tid & 31;            // 0..31
    const int r0 = rg * 8, j0 = jg * 4;
    const float4 b4 = *(const float4*)&bias[j0];
    const int numTiles = (N_NODES + 127) / 128;   // 391

    for (int tile = blockIdx.x; tile < numTiles; tile += gridDim.x) {
        const int row0 = tile * 128;
        __syncthreads();
        // stage A tile [128][K] (float4 per thread-iter)
        for (int idx = tid; idx < 128 * (K / 4); idx += 512) {
            int r = idx >> 5, kq = (idx & 31) * 4;
            int row = row0 + r;
            float4 v = make_float4(0.f, 0.f, 0.f, 0.f);
            if (row < N_NODES) v = *(const float4*)&feat[row * K + kq];
            *(float4*)&sA[r * (K + 4) + kq] = v;
        }
        __syncthreads();

        float4 acc[8];
        #pragma unroll
        for (int i = 0; i < 8; i++) acc[i] = b4;

        #pragma unroll 2
        for (int kk = 0; kk < K; kk += 4) {
            float4 w0 = *(const float4*)&sWT[(kk + 0) * 128 + j0];
            float4 w1 = *(const float4*)&sWT[(kk + 1) * 128 + j0];
            float4 w2 = *(const float4*)&sWT[(kk + 2) * 128 + j0];
            float4 w3 = *(const float4*)&sWT[(kk + 3) * 128 + j0];
            #pragma unroll
            for (int i = 0; i < 8; i++) {
                float4 a = *(const float4*)&sA[(r0 + i) * (K + 4) + kk];
                acc[i].x += a.x * w0.x + a.y * w1.x + a.z * w2.x + a.w * w3.x;
                acc[i].y += a.x * w0.y + a.y * w1.y + a.z * w2.y + a.w * w3.y;
                acc[i].z += a.x * w0.z + a.y * w1.z + a.z * w2.z + a.w * w3.z;
                acc[i].w += a.x * w0.w + a.y * w1.w + a.z * w2.w + a.w * w3.w;
            }
        }
        #pragma unroll
        for (int i = 0; i < 8; i++) {
            int row = row0 + r0 + i;
            if (row < N_NODES) *(float4*)&g_h[row * D + j0] = acc[i];
        }
    }
}

// ---------------------------------------------------------------------------
// GEMM2: out = concat(feat, neigh) @ W_neigh^T + b  (K=256, two 128-k chunks)
// ---------------------------------------------------------------------------
__global__ void __launch_bounds__(512, 1)
gemm_out_kernel(const float* __restrict__ feat,
                const float* __restrict__ W,
                const float* __restrict__ bias,
                float* __restrict__ out) {
    const int K = 256, KC = 128;
    extern __shared__ float sh[];
    float* sWT = sh;                 // [256][128] k-major, 128KB
    float* sA  = sh + K * 128;       // [128][KC+4]
    const int tid = threadIdx.x;

    {
        int j = tid & 127;
        for (int kb = (tid >> 7) * 4; kb < K; kb += 16) {
            float4 v = *(const float4*)&W[j * K + kb];
            sWT[(kb + 0) * 128 + j] = v.x;
            sWT[(kb + 1) * 128 + j] = v.y;
            sWT[(kb + 2) * 128 + j] = v.z;
            sWT[(kb + 3) * 128 + j] = v.w;
        }
    }

    const int rg = tid >> 5;
    const int jg = tid & 31;
    const int r0 = rg * 8, j0 = jg * 4;
    const float4 b4 = *(const float4*)&bias[j0];
    const int numTiles = (N_NODES + 127) / 128;

    for (int tile = blockIdx.x; tile < numTiles; tile += gridDim.x) {
        const int row0 = tile * 128;
        float4 acc[8];
        #pragma unroll
        for (int i = 0; i < 8; i++) acc[i] = b4;

        #pragma unroll
        for (int c = 0; c < 2; c++) {
            __syncthreads();
            const float* srcbuf = (c == 0) ? feat : g_neigh;
            for (int idx = tid; idx < 128 * (KC / 4); idx += 512) {
                int r = idx >> 5, kq = (idx & 31) * 4;
                int row = row0 + r;
                float4 v = make_float4(0.f, 0.f, 0.f, 0.f);
                if (row < N_NODES) v = *(const float4*)&srcbuf[row * D + kq];
                *(float4*)&sA[r * (KC + 4) + kq] = v;
            }
            __syncthreads();

            const float* wbase = sWT + c * KC * 128;
            #pragma unroll 2
            for (int kk = 0; kk < KC; kk += 4) {
                float4 w0 = *(const float4*)&wbase[(kk + 0) * 128 + j0];
                float4 w1 = *(const float4*)&wbase[(kk + 1) * 128 + j0];
                float4 w2 = *(const float4*)&wbase[(kk + 2) * 128 + j0];
                float4 w3 = *(const float4*)&wbase[(kk + 3) * 128 + j0];
                #pragma unroll
                for (int i = 0; i < 8; i++) {
                    float4 a = *(const float4*)&sA[(r0 + i) * (KC + 4) + kk];
                    acc[i].x += a.x * w0.x + a.y * w1.x + a.z * w2.x + a.w * w3.x;
                    acc[i].y += a.x * w0.y + a.y * w1.y + a.z * w2.y + a.w * w3.y;
                    acc[i].z += a.x * w0.z + a.y * w1.z + a.z * w2.z + a.w * w3.z;
                    acc[i].w += a.x * w0.w + a.y * w1.w + a.z * w2.w + a.w * w3.w;
                }
            }
        }

        #pragma unroll
        for (int i = 0; i < 8; i++) {
            int row = row0 + r0 + i;
            if (row < N_NODES) *(float4*)&out[row * 128 + j0] = acc[i];
        }
    }
}

// ---------------------------------------------------------------------------
extern "C" void kernel_launch(void* const* d_in, const int* in_sizes, int n_in,
                              void* d_out, int out_size) {
    const float* feat    = (const float*)d_in[0];
    const float* weight  = (const float*)d_in[1];
    const void*  src     = d_in[2];
    const void*  dst     = d_in[3];
    const float* W_pool  = (const float*)d_in[4];
    const float* b_pool  = (const float*)d_in[5];
    const float* W_neigh = (const float*)d_in[6];
    const float* b_neigh = (const float*)d_in[7];
    float* out = (float*)d_out;

    const int shm1 = (128 * 128 + 128 * 132) * sizeof(float);   // 133 KB
    const int shm2 = (256 * 128 + 128 * 132) * sizeof(float);   // 198.6 KB... (256*128+128*132)*4 = 198656 B
    cudaFuncSetAttribute(gemm_pool_kernel, cudaFuncAttributeMaxDynamicSharedMemorySize, shm1);
    cudaFuncSetAttribute(gemm_out_kernel,  cudaFuncAttributeMaxDynamicSharedMemorySize, shm2);

    const int nbScan = (N_NODES + 511) / 512;        // 98
    const int nbEdge = (N_EDGES + 511) / 512;        // 1250

    detect_kernel<<<1, 1>>>((const int*)src);
    zero_deg_kernel<<<nbScan, 512>>>();
    hist_kernel<<<nbEdge, 512>>>(dst);
    scan1_kernel<<<nbScan, 512>>>();
    scan2_kernel<<<1, 1>>>(nbScan);
    scan3_kernel<<<nbScan, 512>>>();
    scatter_kernel<<<nbEdge, 512>>>(src, dst, weight);
    gemm_pool_kernel<<<148, 512, shm1>>>(feat, W_pool, b_pool);
    gather_kernel<<<(N_NODES + 7) / 8, 256>>>();
    gemm_out_kernel<<<148, 512, shm2>>>(feat, W_neigh, b_neigh, out);
}

// round 10
// speedup vs baseline: 4.7927x; 1.4713x over previous
#include <cuda_runtime.h>
#include <cuda_bf16.h>
#include <math_constants.h>
#include <cstdint>

#define N_NODES 50000
#define N_EDGES 640000
#define D 128

// ---------------- scratch ----------------
__device__ float g_h[N_NODES * D];
__device__ float g_neigh[N_NODES * D];
__device__ int   g_deg[N_NODES];
__device__ int   g_off[N_NODES + 1];
__device__ int   g_cur[N_NODES];
__device__ int   g_bsum[128];
__device__ int   g_boff[128];
__device__ int   g_srcs[N_EDGES];
__device__ float g_ws[N_EDGES];
__device__ int   g_is64;

// =========================== helpers ===================================
__device__ __forceinline__ uint32_t smem_u32(const void* p) {
    uint32_t a;
    asm("{ .reg .u64 t; cvta.to.shared.u64 t, %1; cvt.u32.u64 %0, t; }" : "=r"(a) : "l"(p));
    return a;
}
__device__ __forceinline__ void ldsm_x4(uint32_t addr, uint32_t* r) {
    asm volatile("ldmatrix.sync.aligned.m8n8.x4.shared.b16 {%0,%1,%2,%3}, [%4];"
                 : "=r"(r[0]), "=r"(r[1]), "=r"(r[2]), "=r"(r[3]) : "r"(addr));
}
__device__ __forceinline__ void mma_bf16(float* c, const uint32_t* a, uint32_t b0, uint32_t b1) {
    asm volatile(
        "mma.sync.aligned.m16n8k16.row.col.f32.bf16.bf16.f32 "
        "{%0,%1,%2,%3}, {%4,%5,%6,%7}, {%8,%9}, {%0,%1,%2,%3};"
        : "+f"(c[0]), "+f"(c[1]), "+f"(c[2]), "+f"(c[3])
        : "r"(a[0]), "r"(a[1]), "r"(a[2]), "r"(a[3]), "r"(b0), "r"(b1));
}
// split fp32 pair -> packed bf16x2 hi and lo
__device__ __forceinline__ void split2(float x, float y, uint32_t& hi, uint32_t& lo) {
    __nv_bfloat16 hx = __float2bfloat16(x), hy = __float2bfloat16(y);
    float lx = x - __bfloat162float(hx), ly = y - __bfloat162float(hy);
    __nv_bfloat162 h = __halves2bfloat162(hx, hy);
    __nv_bfloat162 l = __halves2bfloat162(__float2bfloat16(lx), __float2bfloat16(ly));
    hi = *(uint32_t*)&h;
    lo = *(uint32_t*)&l;
}

// ===========================================================================
// small build kernels
// ===========================================================================
__global__ void detect_kernel(const int* __restrict__ s32) {
    int ok = 1;
    for (int i = 1; i < 64; i += 2)
        if (s32[i] != 0) { ok = 0; break; }
    g_is64 = ok;
}
__global__ void zero_deg_kernel() {
    int i = blockIdx.x * blockDim.x + threadIdx.x;
    if (i < N_NODES) g_deg[i] = 0;
}
__global__ void hist_kernel(const void* __restrict__ dstp) {
    int e = blockIdx.x * blockDim.x + threadIdx.x;
    if (e >= N_EDGES) return;
    int d = g_is64 ? (int)((const long long*)dstp)[e] : ((const int*)dstp)[e];
    atomicAdd(&g_deg[d], 1);
}
__global__ void scan1_kernel() {
    __shared__ int tmp[512];
    int t = threadIdx.x, i = blockIdx.x * 512 + t;
    int v = (i < N_NODES) ? g_deg[i] : 0;
    tmp[t] = v;
    __syncthreads();
    for (int off = 1; off < 512; off <<= 1) {
        int x = tmp[t];
        if (t >= off) x += tmp[t - off];
        __syncthreads();
        tmp[t] = x;
        __syncthreads();
    }
    int incl = tmp[t];
    if (i < N_NODES) g_off[i] = incl - v;
    if (t == 511) g_bsum[blockIdx.x] = incl;
}
__global__ void scan2_kernel(int nb) {
    int run = 0;
    for (int b = 0; b < nb; b++) { g_boff[b] = run; run += g_bsum[b]; }
    g_off[N_NODES] = run;
}
__global__ void scan3_kernel() {
    int i = blockIdx.x * 512 + threadIdx.x;
    if (i < N_NODES) {
        int o = g_off[i] + g_boff[blockIdx.x];
        g_off[i] = o;
        g_cur[i] = o;
    }
}
__global__ void scatter_kernel(const void* __restrict__ srcp,
                               const void* __restrict__ dstp,
                               const float* __restrict__ w) {
    int e = blockIdx.x * blockDim.x + threadIdx.x;
    if (e >= N_EDGES) return;
    int s, d;
    if (g_is64) {
        s = (int)((const long long*)srcp)[e];
        d = (int)((const long long*)dstp)[e];
    } else {
        s = ((const int*)srcp)[e];
        d = ((const int*)dstp)[e];
    }
    int pos = atomicAdd(&g_cur[d], 1);
    g_srcs[pos] = s;
    g_ws[pos]   = w[e];
}

// ---------------------------------------------------------------------------
// Gather-max: one warp per node (atomic-free, order-invariant)
// ---------------------------------------------------------------------------
__global__ void gather_kernel() {
    const int node = blockIdx.x * 8 + (threadIdx.x >> 5);
    const int lane = threadIdx.x & 31;
    if (node >= N_NODES) return;
    const int beg = g_off[node], end = g_off[node + 1];

    float4 acc = make_float4(-CUDART_INF_F, -CUDART_INF_F, -CUDART_INF_F, -CUDART_INF_F);
    int e = beg;
    for (; e + 1 < end; e += 2) {
        int   s0 = g_srcs[e],   s1 = g_srcs[e + 1];
        float w0 = g_ws[e],     w1 = g_ws[e + 1];
        float4 h0 = *(const float4*)&g_h[s0 * D + lane * 4];
        float4 h1 = *(const float4*)&g_h[s1 * D + lane * 4];
        acc.x = fmaxf(acc.x, h0.x * w0); acc.y = fmaxf(acc.y, h0.y * w0);
        acc.z = fmaxf(acc.z, h0.z * w0); acc.w = fmaxf(acc.w, h0.w * w0);
        acc.x = fmaxf(acc.x, h1.x * w1); acc.y = fmaxf(acc.y, h1.y * w1);
        acc.z = fmaxf(acc.z, h1.z * w1); acc.w = fmaxf(acc.w, h1.w * w1);
    }
    if (e < end) {
        int s0 = g_srcs[e]; float w0 = g_ws[e];
        float4 h0 = *(const float4*)&g_h[s0 * D + lane * 4];
        acc.x = fmaxf(acc.x, h0.x * w0); acc.y = fmaxf(acc.y, h0.y * w0);
        acc.z = fmaxf(acc.z, h0.z * w0); acc.w = fmaxf(acc.w, h0.w * w0);
    }
    if (beg == end) acc = make_float4(0.f, 0.f, 0.f, 0.f);
    *(float4*)&g_neigh[node * D + lane * 4] = acc;
}

// ===========================================================================
// Tensor-core GEMM via mma.sync (bf16 3-term split, fp32 accum in registers)
//   mode 0: g_h = feat @ W_pool^T + b               (K=128, 1 pass)
//   mode 1: out = [feat | g_neigh] @ W_neigh^T + b  (K=256, 2 passes)
// Block 256 thr = 8 warps (4 x 2), block tile 128x128, warp tile 32x64.
// SMEM: A_hi[128][136], A_lo[128][136] bf16; W_hi/W_lo [128][K+8] bf16.
// B fragments: W smem is n-major (row=n, contig k) -> NON-trans ldmatrix.
// ===========================================================================
#define STRIDE_A 136

__global__ void __launch_bounds__(256, 1)
gemm_mma_kernel(const float* __restrict__ feat,
                const float* __restrict__ W,
                const float* __restrict__ bias,
                float* __restrict__ out_ext,
                int mode) {
    extern __shared__ char sh[];
    const int npass = mode ? 2 : 1;
    const int K = npass * 128;
    const int strideW = K + 8;

    __nv_bfloat16* sAhi = (__nv_bfloat16*)sh;
    __nv_bfloat16* sAlo = sAhi + 128 * STRIDE_A;
    __nv_bfloat16* sWhi = sAlo + 128 * STRIDE_A;
    __nv_bfloat16* sWlo = sWhi + 128 * strideW;
    const uint32_t bAhi = smem_u32(sAhi);
    const uint32_t bAlo = smem_u32(sAlo);
    const uint32_t bWhi = smem_u32(sWhi);
    const uint32_t bWlo = smem_u32(sWlo);

    float* outp = mode ? out_ext : g_h;
    const int tid = threadIdx.x, wid = tid >> 5, lane = tid & 31;

    // ---- stage W hi/lo ----
    {
        const int K4 = K / 4;
        for (int idx = tid; idx < 128 * K4; idx += 256) {
            int r = idx / K4, k = (idx % K4) * 4;
            float4 v = *(const float4*)&W[r * K + k];
            uint32_t h0, l0, h1, l1;
            split2(v.x, v.y, h0, l0);
            split2(v.z, v.w, h1, l1);
            *(uint32_t*)&sWhi[r * strideW + k]     = h0;
            *(uint32_t*)&sWhi[r * strideW + k + 2] = h1;
            *(uint32_t*)&sWlo[r * strideW + k]     = l0;
            *(uint32_t*)&sWlo[r * strideW + k + 2] = l1;
        }
    }

    const int warp_m = wid & 3;          // 0..3 -> 32-row stripes
    const int warp_n = wid >> 2;         // 0..1 -> 64-col stripes
    const int r0 = warp_m * 32;
    const int c0 = warp_n * 64;
    const int lrow = lane & 15, lhalf = lane >> 4;
    const int qrow = lane >> 2, qcol = (lane & 3) * 2;

    // bias preload (per n8 fragment column pair)
    float2 bias2[8];
    #pragma unroll
    for (int f = 0; f < 8; f++) {
        int c = c0 + f * 8 + qcol;
        bias2[f] = make_float2(bias[c], bias[c + 1]);
    }
    __syncthreads();

    const int numTiles = (N_NODES + 127) / 128;   // 391

    for (int tile = blockIdx.x; tile < numTiles; tile += gridDim.x) {
        const int row0 = tile * 128;
        float c[2][8][4];
        #pragma unroll
        for (int mt = 0; mt < 2; mt++)
            #pragma unroll
            for (int f = 0; f < 8; f++) {
                c[mt][f][0] = bias2[f].x; c[mt][f][1] = bias2[f].y;
                c[mt][f][2] = bias2[f].x; c[mt][f][3] = bias2[f].y;
            }

        for (int p = 0; p < npass; p++) {
            const float* srcbuf = (p == 0) ? feat : g_neigh;
            __syncthreads();
            // ---- stage A hi/lo ----
            for (int idx = tid; idx < 128 * 32; idx += 256) {
                int r = idx >> 5, k = (idx & 31) * 4;
                int row = row0 + r;
                float4 v = make_float4(0.f, 0.f, 0.f, 0.f);
                if (row < N_NODES) v = *(const float4*)&srcbuf[row * D + k];
                uint32_t h0, l0, h1, l1;
                split2(v.x, v.y, h0, l0);
                split2(v.z, v.w, h1, l1);
                *(uint32_t*)&sAhi[r * STRIDE_A + k]     = h0;
                *(uint32_t*)&sAhi[r * STRIDE_A + k + 2] = h1;
                *(uint32_t*)&sAlo[r * STRIDE_A + k]     = l0;
                *(uint32_t*)&sAlo[r * STRIDE_A + k + 2] = l1;
            }
            __syncthreads();

            const int kglob0 = p * 128;
            #pragma unroll
            for (int ks = 0; ks < 8; ks++) {
                uint32_t ah[2][4], al[2][4];
                #pragma unroll
                for (int mt = 0; mt < 2; mt++) {
                    uint32_t off = (uint32_t)(((r0 + mt * 16 + lrow) * STRIDE_A
                                    + ks * 16 + lhalf * 8) * 2);
                    ldsm_x4(bAhi + off, ah[mt]);
                    ldsm_x4(bAlo + off, al[mt]);
                }
                uint32_t wh[4][4], wl[4][4];
                #pragma unroll
                for (int g = 0; g < 4; g++) {
                    uint32_t off = (uint32_t)(((c0 + g * 16 + lrow) * strideW
                                    + kglob0 + ks * 16 + lhalf * 8) * 2);
                    ldsm_x4(bWhi + off, wh[g]);     // non-trans: n-major tile
                    ldsm_x4(bWlo + off, wl[g]);
                }
                #pragma unroll
                for (int g = 0; g < 4; g++) {
                    #pragma unroll
                    for (int mt = 0; mt < 2; mt++) {
                        mma_bf16(c[mt][2 * g],     ah[mt], wh[g][0], wh[g][2]);
                        mma_bf16(c[mt][2 * g + 1], ah[mt], wh[g][1], wh[g][3]);
                        mma_bf16(c[mt][2 * g],     al[mt], wh[g][0], wh[g][2]);
                        mma_bf16(c[mt][2 * g + 1], al[mt], wh[g][1], wh[g][3]);
                        mma_bf16(c[mt][2 * g],     ah[mt], wl[g][0], wl[g][2]);
                        mma_bf16(c[mt][2 * g + 1], ah[mt], wl[g][1], wl[g][3]);
                    }
                }
            }
        }

        // ---- epilogue: direct stores ----
        #pragma unroll
        for (int mt = 0; mt < 2; mt++) {
            int r = row0 + r0 + mt * 16 + qrow;
            #pragma unroll
            for (int f = 0; f < 8; f++) {
                int cc = c0 + f * 8 + qcol;
                if (r < N_NODES)
                    *(float2*)&outp[r * 128 + cc] = make_float2(c[mt][f][0], c[mt][f][1]);
                if (r + 8 < N_NODES)
                    *(float2*)&outp[(r + 8) * 128 + cc] = make_float2(c[mt][f][2], c[mt][f][3]);
            }
        }
    }
}

// ---------------------------------------------------------------------------
extern "C" void kernel_launch(void* const* d_in, const int* in_sizes, int n_in,
                              void* d_out, int out_size) {
    const float* feat    = (const float*)d_in[0];
    const float* weight  = (const float*)d_in[1];
    const void*  src     = d_in[2];
    const void*  dst     = d_in[3];
    const float* W_pool  = (const float*)d_in[4];
    const float* b_pool  = (const float*)d_in[5];
    const float* W_neigh = (const float*)d_in[6];
    const float* b_neigh = (const float*)d_in[7];
    float* out = (float*)d_out;

    const int shmA  = 2 * 128 * STRIDE_A * 2;                 // 69632
    const int shm1  = shmA + 2 * 128 * (128 + 8) * 2;         // 139264
    const int shm2  = shmA + 2 * 128 * (256 + 8) * 2;         // 204800
    cudaFuncSetAttribute(gemm_mma_kernel, cudaFuncAttributeMaxDynamicSharedMemorySize, shm2);

    const int nbScan = (N_NODES + 511) / 512;
    const int nbEdge = (N_EDGES + 511) / 512;

    detect_kernel<<<1, 1>>>((const int*)src);
    zero_deg_kernel<<<nbScan, 512>>>();
    hist_kernel<<<nbEdge, 512>>>(dst);
    scan1_kernel<<<nbScan, 512>>>();
    scan2_kernel<<<1, 1>>>(nbScan);
    scan3_kernel<<<nbScan, 512>>>();
    scatter_kernel<<<nbEdge, 512>>>(src, dst, weight);
    gemm_mma_kernel<<<148, 256, shm1>>>(feat, W_pool, b_pool, nullptr, 0);
    gather_kernel<<<(N_NODES + 7) / 8, 256>>>();
    gemm_mma_kernel<<<148, 256, shm2>>>(feat, W_neigh, b_neigh, out, 1);
}